// round 3
// baseline (speedup 1.0000x reference)
#include <cuda_runtime.h>

// out[p, :] = cumsum(W, axis=1)[:, x[p]] + b, p in [0, 8192*200)
// x: int32 (8192*200), W: fp32 (64,129) row-major, b: fp32 (64), out: fp32 (NPOS*64)

#define F1 129                  // num_feature + 1
#define D  64                   // vector dim
#define NPOS (8192 * 200)       // 1,638,400 positions (divisible by 32)
#define TPB 256                 // threads per block
#define WARPS_PB (TPB / 32)

// Precomputed lookup table: g_table[c*D + d] = b[d] + sum_{j<=c} W[d*F1 + j]
__device__ float g_table[F1 * D];

__global__ void build_table_kernel(const float* __restrict__ W,
                                   const float* __restrict__ b) {
    int d = threadIdx.x;          // 0..63, one output dim per thread
    if (d >= D) return;
    float s = b[d];
    const float* wrow = W + d * F1;
    #pragma unroll 1
    for (int c = 0; c < F1; ++c) {
        s += wrow[c];
        g_table[c * D + d] = s;   // transposed: row c holds the 64-dim output for x==c
    }
}

__global__ void __launch_bounds__(TPB, 6)
embed_kernel(const int* __restrict__ x, float* __restrict__ out) {
    // Shared table: 129 rows * 16 float4 = 33,024 bytes
    __shared__ float4 tab[F1 * (D / 4)];

    const float4* gt = reinterpret_cast<const float4*>(g_table);
    #pragma unroll 1
    for (int i = threadIdx.x; i < F1 * (D / 4); i += TPB)
        tab[i] = gt[i];
    __syncthreads();

    const int lane   = threadIdx.x & 31;
    const int lane15 = lane & 15;          // which float4 within the 64-float row
    const int half   = lane >> 4;          // 0 or 1: which of the pair of positions
    const int warp   = threadIdx.x >> 5;

    const int gwarp      = blockIdx.x * WARPS_PB + warp;
    const int nwarps     = gridDim.x * WARPS_PB;
    float4* __restrict__ o4 = reinterpret_cast<float4*>(out);

    // Each warp handles 32 consecutive positions per outer iteration:
    // one coalesced LDG of 32 x-values, then 16 independent LDS.128->STG.128 chains.
    #pragma unroll 1
    for (int base = gwarp * 32; base < NPOS; base += nwarps * 32) {
        const int xv = x[base + lane];                 // coalesced 128B load
        #pragma unroll
        for (int k = 0; k < 16; ++k) {
            const int xi = __shfl_sync(0xffffffffu, xv, 2 * k + half);
            const float4 v = tab[xi * (D / 4) + lane15];
            // warp stores 2 consecutive positions = 512B contiguous
            __stcs(&o4[(size_t)(base + 2 * k + half) * (D / 4) + lane15], v);
        }
    }
}

extern "C" void kernel_launch(void* const* d_in, const int* in_sizes, int n_in,
                              void* d_out, int out_size) {
    const int*   x = (const int*)  d_in[0];
    const float* W = (const float*)d_in[1];
    const float* b = (const float*)d_in[2];
    float*     out = (float*)d_out;

    build_table_kernel<<<1, 64>>>(W, b);

    // Persistent grid: 152 SMs * 6 CTAs (smem-limited at 33KB/CTA)
    const int grid = 152 * 6;
    embed_kernel<<<grid, TPB>>>(x, out);
}

// round 4
// speedup vs baseline: 1.2390x; 1.2390x over previous
#include <cuda_runtime.h>

// out[p, :] = cumsum(W, axis=1)[:, x[p]] + b, p in [0, 8192*200)
// x: int32 (NPOS), W: fp32 (64,129) row-major, b: fp32 (64), out: fp32 (NPOS*64)

#define F1 129                  // num_feature + 1
#define D  64                   // vector dim
#define NPOS (8192 * 200)       // 1,638,400 positions (divisible by 32)
#define TPB 256
#define WARPS_PB (TPB / 32)

__global__ void __launch_bounds__(TPB, 6)
embed_kernel(const int* __restrict__ x,
             const float* __restrict__ W,
             const float* __restrict__ b,
             float* __restrict__ out) {
    // Shared table: tab[c*64 + d] = b[d] + sum_{j<=c} W[d*F1 + j]; 33,024 B
    __shared__ float tab[F1 * D];

    // ---- fused table build: threads 0..63, batched loads to keep the ----
    // ---- FADD chain (not memory latency) on the critical path        ----
    const int t = threadIdx.x;
    if (t < D) {
        const float* wrow = W + t * F1;
        float s = b[t];
        #pragma unroll 1
        for (int c0 = 0; c0 < 128; c0 += 8) {
            float v[8];
            #pragma unroll
            for (int j = 0; j < 8; ++j) v[j] = __ldg(&wrow[c0 + j]);
            #pragma unroll
            for (int j = 0; j < 8; ++j) {
                s += v[j];
                tab[(c0 + j) * D + t] = s;   // threads 0..63 -> consecutive addrs, no conflicts
            }
        }
        s += __ldg(&wrow[128]);
        tab[128 * D + t] = s;
    }
    __syncthreads();

    const float4* tab4 = reinterpret_cast<const float4*>(tab);

    const int lane   = threadIdx.x & 31;
    const int lane15 = lane & 15;          // which float4 within the 64-float row
    const int half   = lane >> 4;          // 0/1: which of each pair of positions
    const int warp   = threadIdx.x >> 5;

    const int gwarp  = blockIdx.x * WARPS_PB + warp;
    const int nwarps = gridDim.x * WARPS_PB;
    const int stride = nwarps * 32;
    float4* __restrict__ o4 = reinterpret_cast<float4*>(out);

    int base = gwarp * 32;
    if (base >= NPOS) return;

    int xv = x[base + lane];                       // coalesced 128B load
    #pragma unroll 1
    for (; base < NPOS; base += stride) {
        // prefetch next iteration's x-vector off the critical path
        const int nbase = base + stride;
        int xv_next = 0;
        if (nbase < NPOS) xv_next = x[nbase + lane];

        #pragma unroll
        for (int k = 0; k < 16; ++k) {
            const int xi = __shfl_sync(0xffffffffu, xv, 2 * k + half);
            const float4 v = tab4[xi * (D / 4) + lane15];
            // warp stores 2 consecutive positions = 512B contiguous, streaming
            __stcs(&o4[(size_t)(base + 2 * k + half) * (D / 4) + lane15], v);
        }
        xv = xv_next;
    }
}

extern "C" void kernel_launch(void* const* d_in, const int* in_sizes, int n_in,
                              void* d_out, int out_size) {
    const int*   x = (const int*)  d_in[0];
    const float* W = (const float*)d_in[1];
    const float* b = (const float*)d_in[2];
    float*     out = (float*)d_out;

    // Persistent grid: 152 SMs * 6 CTAs (smem-limited at 33KB/CTA)
    const int grid = 152 * 6;
    embed_kernel<<<grid, TPB>>>(x, W, b, out);
}

// round 5
// speedup vs baseline: 1.2448x; 1.0047x over previous
#include <cuda_runtime.h>

// out[p, :] = cumsum(W, axis=1)[:, x[p]] + b, p in [0, 8192*200)
// x: int32 (NPOS), W: fp32 (64,129) row-major, b: fp32 (64), out: fp32 (NPOS*64)

#define F1 129                  // num_feature + 1
#define D  64                   // vector dim
#define NPOS (8192 * 200)       // 1,638,400 positions (divisible by 32)
#define TPB 256
#define WARPS_PB (TPB / 32)

__global__ void __launch_bounds__(TPB, 6)
embed_kernel(const int* __restrict__ x,
             const float* __restrict__ W,
             const float* __restrict__ b,
             float* __restrict__ out) {
    // Shared table: tab[c*64 + d] = b[d] + sum_{j<=c} W[d*F1 + j]; 33,024 B
    __shared__ float tab[F1 * D];

    // ---- fused table build (threads 0..63): batched loads keep the ----
    // ---- FADD chain, not memory latency, on the critical path      ----
    const int t = threadIdx.x;
    if (t < D) {
        const float* wrow = W + t * F1;
        float s = b[t];
        #pragma unroll 1
        for (int c0 = 0; c0 < 128; c0 += 8) {
            float v[8];
            #pragma unroll
            for (int j = 0; j < 8; ++j) v[j] = __ldg(&wrow[c0 + j]);
            #pragma unroll
            for (int j = 0; j < 8; ++j) {
                s += v[j];
                tab[(c0 + j) * D + t] = s;
            }
        }
        s += __ldg(&wrow[128]);
        tab[128 * D + t] = s;
    }
    __syncthreads();

    const float4* tab4 = reinterpret_cast<const float4*>(tab);

    const int lane   = threadIdx.x & 31;
    const int lane15 = lane & 15;          // which float4 within the 64-float row
    const int half   = lane >> 4;          // 0/1: which of each pair of positions
    const int warp   = threadIdx.x >> 5;

    const int gwarp  = blockIdx.x * WARPS_PB + warp;
    const int nwarps = gridDim.x * WARPS_PB;
    const int stride = nwarps * 32;        // positions per warp per outer iter
    float4* __restrict__ o4 = reinterpret_cast<float4*>(out);

    int base = gwarp * 32;
    if (base >= NPOS) return;

    int xv = x[base + lane];                       // coalesced 128B load
    #pragma unroll 1
    for (; base < NPOS; base += stride) {
        // ---- Phase A: all 16 broadcast indices up front (independent) ----
        int idx[16];
        #pragma unroll
        for (int k = 0; k < 16; ++k)
            idx[k] = __shfl_sync(0xffffffffu, xv, 2 * k + half) * (D / 4) + lane15;

        // prefetch next iteration's x-vector off the critical path
        const int nbase = base + stride;
        int xv_next = 0;
        if (nbase < NPOS) xv_next = x[nbase + lane];

        // ---- Phase B: 16 independent LDS.128 -> STG.128 chains.       ----
        // Store addresses differ only by k*512B -> immediate offsets off
        // a single base register; ptxas can software-pipeline deeply.
        float4* wbase = o4 + ((size_t)base + half) * (D / 4) + lane15;
        #pragma unroll
        for (int k = 0; k < 16; ++k) {
            const float4 v = tab4[idx[k]];
            __stcs(wbase + k * 2 * (D / 4), v);    // k*512 bytes
        }
        xv = xv_next;
    }
}

extern "C" void kernel_launch(void* const* d_in, const int* in_sizes, int n_in,
                              void* d_out, int out_size) {
    const int*   x = (const int*)  d_in[0];
    const float* W = (const float*)d_in[1];
    const float* b = (const float*)d_in[2];
    float*     out = (float*)d_out;

    // Persistent grid: 152 SMs * 6 CTAs (smem-limited at 33KB/CTA)
    const int grid = 152 * 6;
    embed_kernel<<<grid, TPB>>>(x, W, b, out);
}